// round 5
// baseline (speedup 1.0000x reference)
#include <cuda_runtime.h>
#include <math.h>

#define NB 8
#define NT 2048
#define NE 64
#define NH 8
#define NDK 8
#define NFF 256
#define NTOK (NB*NT)
#define W2T_STRIDE 68

typedef unsigned long long u64;

// ---- scratch (static device globals) ----
__device__ float g_Q[NTOK*NE];
__device__ float g_K[NTOK*NE];
__device__ float g_V[NTOK*NE];
__device__ float g_attn[NTOK*NE];
__device__ float g_x1[NTOK*NE];
__device__ float g_qo[NTOK*NE];

// ---- f32x2 packed helpers ----
__device__ __forceinline__ u64 pk(float a, float b) {
    u64 r; asm("mov.b64 %0,{%1,%2};" : "=l"(r) : "f"(a), "f"(b)); return r;
}
__device__ __forceinline__ void upk(u64 v, float& a, float& b) {
    asm("mov.b64 {%0,%1},%2;" : "=f"(a), "=f"(b) : "l"(v));
}
__device__ __forceinline__ u64 f2mul(u64 a, u64 b) {
    u64 r; asm("mul.rn.f32x2 %0,%1,%2;" : "=l"(r) : "l"(a), "l"(b)); return r;
}
__device__ __forceinline__ u64 f2fma(u64 a, u64 b, u64 c) {
    u64 r; asm("fma.rn.f32x2 %0,%1,%2,%3;" : "=l"(r) : "l"(a), "l"(b), "l"(c)); return r;
}
__device__ __forceinline__ u64 f2add(u64 a, u64 b) {
    u64 r; asm("add.rn.f32x2 %0,%1,%2;" : "=l"(r) : "l"(a), "l"(b)); return r;
}
__device__ __forceinline__ void lds16(unsigned addr, u64& a, u64& b) {
    asm volatile("ld.shared.v2.u64 {%0,%1},[%2];" : "=l"(a), "=l"(b) : "r"(addr));
}
__device__ __forceinline__ float ex2f(float x) {
    float r; asm("ex2.approx.f32 %0,%1;" : "=f"(r) : "f"(x)); return r;
}
__device__ __forceinline__ unsigned smaddr(const void* p) {
    unsigned r;
    asm("{ .reg .u64 t; cvta.to.shared.u64 t, %1; cvt.u32.u64 %0, t; }" : "=r"(r) : "l"(p));
    return r;
}

// 64-float dot: smem row (broadcast) vs packed register vector a2[32].
__device__ __forceinline__ float dot64(unsigned addr, const u64* a2) {
    u64 w0, w1, s0, s1;
    lds16(addr, w0, w1);
    s0 = f2mul(a2[0], w0);
    s1 = f2mul(a2[1], w1);
#pragma unroll
    for (int t = 1; t < 16; ++t) {
        lds16(addr + t*16, w0, w1);
        s0 = f2fma(a2[2*t],   w0, s0);
        s1 = f2fma(a2[2*t+1], w1, s1);
    }
    s0 = f2add(s0, s1);
    float lo, hi; upk(s0, lo, hi);
    return lo + hi;
}

// ============================================================
// K1: QKV proj + bias + cos(.+theta). 512 thr = 128 tokens x 4 j-slices.
// ============================================================
__global__ void __launch_bounds__(512) k_qkv(
    const float* __restrict__ x,
    const float* __restrict__ Wq, const float* __restrict__ bq,
    const float* __restrict__ Wk, const float* __restrict__ bk,
    const float* __restrict__ Wv, const float* __restrict__ bv,
    const float* __restrict__ thA)
{
    extern __shared__ float sm[];
    float* Wqs = sm;
    float* Wks = sm + 4096;
    float* Wvs = sm + 8192;
    float* bqs = sm + 12288;
    float* bks = sm + 12352;
    float* bvs = sm + 12416;

    for (int i = threadIdx.x; i < 4096; i += 512) {
        Wqs[i] = Wq[i]; Wks[i] = Wk[i]; Wvs[i] = Wv[i];
    }
    if (threadIdx.x < 64) {
        bqs[threadIdx.x] = bq[threadIdx.x];
        bks[threadIdx.x] = bk[threadIdx.x];
        bvs[threadIdx.x] = bv[threadIdx.x];
    }
    __syncthreads();

    int tok   = blockIdx.x * 128 + (threadIdx.x & 127);
    int slice = threadIdx.x >> 7;          // 0..3 (warp-uniform)

    u64 xr2[32];
    const float4* xp = (const float4*)(x + (size_t)tok * NE);
#pragma unroll
    for (int c = 0; c < 16; ++c) {
        float4 t = xp[c];
        xr2[2*c]   = pk(t.x, t.y);
        xr2[2*c+1] = pk(t.z, t.w);
    }
    float th = *thA;
    unsigned wqb = smaddr(Wqs), wkb = smaddr(Wks), wvb = smaddr(Wvs);

    float4* Qo = (float4*)(g_Q + (size_t)tok * NE);
    float4* Ko = (float4*)(g_K + (size_t)tok * NE);
    float4* Vo = (float4*)(g_V + (size_t)tok * NE);

#pragma unroll
    for (int c = 0; c < 4; ++c) {
        float oq[4], ok[4], ov[4];
#pragma unroll
        for (int u = 0; u < 4; ++u) {
            int j = slice*16 + 4*c + u;
            oq[u] = __cosf(dot64(wqb + j*256, xr2) + bqs[j] + th);
            ok[u] = __cosf(dot64(wkb + j*256, xr2) + bks[j] + th);
            ov[u] = __cosf(dot64(wvb + j*256, xr2) + bvs[j] + th);
        }
        Qo[slice*4 + c] = make_float4(oq[0], oq[1], oq[2], oq[3]);
        Ko[slice*4 + c] = make_float4(ok[0], ok[1], ok[2], ok[3]);
        Vo[slice*4 + c] = make_float4(ov[0], ov[1], ov[2], ov[3]);
    }
}

// ============================================================
// K2: attention. 512 threads (16 warps/SM), grid (64 bh, 4 q-tiles).
// K pair-interleaved in smem; softmax without max-subtraction.
// ============================================================
__global__ void __launch_bounds__(512) k_attn()
{
    extern __shared__ float sm[];
    char* smc = (char*)sm;
    int tid = threadIdx.x;
    int bh = blockIdx.x;
    int b = bh >> 3, h = bh & 7;

    const float4* Kg4 = (const float4*)g_K;
    const float4* Vg4 = (const float4*)g_V;
    size_t rowbase = (size_t)b * NT * 16 + h * 2;   // float4 units

    for (int i = tid; i < NT*2; i += 512) {
        int s = i >> 1, half = i & 1;
        float4 t = Kg4[rowbase + (size_t)s*16 + half];
        int p = s >> 1, lane = s & 1;
        char* dst = smc + p*64 + half*32 + lane*4;
        *(float*)(dst +  0) = t.x;
        *(float*)(dst +  8) = t.y;
        *(float*)(dst + 16) = t.z;
        *(float*)(dst + 24) = t.w;
        ((float4*)(smc + 65536))[i] = Vg4[rowbase + (size_t)s*16 + half];
    }
    __syncthreads();

    int q = blockIdx.y * 512 + tid;
    const float QS = 0.35355339059327373f * 1.4426950408889634f; // 1/sqrt(8)*log2e
    float4 qa = ((const float4*)g_Q)[rowbase + (size_t)q*16];
    float4 qb = ((const float4*)g_Q)[rowbase + (size_t)q*16 + 1];
    float t0 = qa.x*QS, t1 = qa.y*QS, t2 = qa.z*QS, t3 = qa.w*QS;
    float t4 = qb.x*QS, t5 = qb.y*QS, t6 = qb.z*QS, t7 = qb.w*QS;
    u64 qd0 = pk(t0,t0), qd1 = pk(t1,t1), qd2 = pk(t2,t2), qd3 = pk(t3,t3);
    u64 qd4 = pk(t4,t4), qd5 = pk(t5,t5), qd6 = pk(t6,t6), qd7 = pk(t7,t7);

    unsigned kb = smaddr(smc);
    unsigned vb = kb + 65536;
    u64 a0 = 0, a1 = 0, a2 = 0, a3 = 0, denP = 0;

#pragma unroll 4
    for (int p = 0; p < NT/2; ++p) {
        u64 p0,p1,p2,p3,p4,p5,p6,p7;
        unsigned ka = kb + p*64;
        lds16(ka,    p0, p1);
        lds16(ka+16, p2, p3);
        lds16(ka+32, p4, p5);
        lds16(ka+48, p6, p7);
        u64 d = f2mul(qd0, p0);
        d = f2fma(qd1, p1, d);
        d = f2fma(qd2, p2, d);
        d = f2fma(qd3, p3, d);
        d = f2fma(qd4, p4, d);
        d = f2fma(qd5, p5, d);
        d = f2fma(qd6, p6, d);
        d = f2fma(qd7, p7, d);
        float lo, hi; upk(d, lo, hi);
        float e0 = ex2f(lo), e1 = ex2f(hi);
        denP = f2add(denP, pk(e0, e1));
        u64 ee0 = pk(e0, e0), ee1 = pk(e1, e1);
        u64 v0,v1,v2,v3,v4,v5,v6,v7;
        unsigned va = vb + p*64;
        lds16(va,    v0, v1);
        lds16(va+16, v2, v3);
        lds16(va+32, v4, v5);
        lds16(va+48, v6, v7);
        a0 = f2fma(ee0, v0, a0);
        a1 = f2fma(ee0, v1, a1);
        a2 = f2fma(ee0, v2, a2);
        a3 = f2fma(ee0, v3, a3);
        a0 = f2fma(ee1, v4, a0);
        a1 = f2fma(ee1, v5, a1);
        a2 = f2fma(ee1, v6, a2);
        a3 = f2fma(ee1, v7, a3);
    }

    float dl, dh; upk(denP, dl, dh);
    float inv = 1.0f / (dl + dh);
    float o0,o1,o2,o3,o4,o5,o6,o7;
    upk(a0, o0, o1); upk(a1, o2, o3); upk(a2, o4, o5); upk(a3, o6, o7);
    float4* op = (float4*)(g_attn + ((size_t)(b*NT + q)) * NE + h * NDK);
    op[0] = make_float4(o0*inv, o1*inv, o2*inv, o3*inv);
    op[1] = make_float4(o4*inv, o5*inv, o6*inv, o7*inv);
}

// ============================================================
// K3: out-proj + residual + LN1 -> x1, qo. 512 thr = 128 tokens x 4 slices,
// staged through smem [j][token].
// ============================================================
__global__ void __launch_bounds__(512) k_oproj(
    const float* __restrict__ x,
    const float* __restrict__ Wo, const float* __restrict__ bo,
    const float* __restrict__ g1, const float* __restrict__ be1,
    const float* __restrict__ thF)
{
    extern __shared__ float sm[];
    float* Wos   = sm;             // 4096
    float* bos   = sm + 4096;      // 64
    float* g1s   = sm + 4160;      // 64
    float* be1s  = sm + 4224;      // 64
    float* stage = sm + 4288;      // 64*128

    for (int i = threadIdx.x; i < 4096; i += 512) Wos[i] = Wo[i];
    if (threadIdx.x < 64) {
        bos[threadIdx.x]  = bo[threadIdx.x];
        g1s[threadIdx.x]  = g1[threadIdx.x];
        be1s[threadIdx.x] = be1[threadIdx.x];
    }
    __syncthreads();

    int tl    = threadIdx.x & 127;             // local token
    int slice = threadIdx.x >> 7;              // 0..3
    int n = blockIdx.x * 128 + tl;

    u64 a2r[32];
    const float4* ap = (const float4*)(g_attn + (size_t)n * NE);
#pragma unroll
    for (int c = 0; c < 16; ++c) {
        float4 t = ap[c];
        a2r[2*c]   = pk(t.x, t.y);
        a2r[2*c+1] = pk(t.z, t.w);
    }
    unsigned wob = smaddr(Wos);

#pragma unroll
    for (int u = 0; u < 16; ++u) {
        int j = slice*16 + u;
        stage[j*128 + tl] = dot64(wob + j*256, a2r) + bos[j];
    }
    __syncthreads();

    if (threadIdx.x < 128) {
        const float4* xp = (const float4*)(x + (size_t)n * NE);
        float o[NE];
        float sum = 0.f, sq = 0.f;
#pragma unroll
        for (int c = 0; c < 16; ++c) {
            float xt[4];
            *(float4*)xt = xp[c];
#pragma unroll
            for (int u = 0; u < 4; ++u) {
                int j = 4*c + u;
                float t = stage[j*128 + tl] + xt[u];
                o[j] = t;
                sum += t;
                sq  += t * t;
            }
        }
        float m = sum * (1.0f/NE);
        float var = sq * (1.0f/NE) - m*m;
        float inv = rsqrtf(var + 1e-5f);
        float cth = __cosf(*thF);

        float4* x1p = (float4*)(g_x1 + (size_t)n * NE);
        float4* qop = (float4*)(g_qo + (size_t)n * NE);
#pragma unroll
        for (int c = 0; c < 16; ++c) {
            float v[4], w[4];
#pragma unroll
            for (int u = 0; u < 4; ++u) {
                int j = 4*c + u;
                v[u] = (o[j] - m) * inv * g1s[j] + be1s[j];
                w[u] = __cosf(v[u]) * cth;
            }
            x1p[c] = make_float4(v[0], v[1], v[2], v[3]);
            qop[c] = make_float4(w[0], w[1], w[2], w[3]);
        }
    }
}

// ============================================================
// K4: FFN + residual + LN2 -> out. 256 thr = 128 tokens x 2 halves of the
// 256 FF rows; partials combined via smem stage.
// ============================================================
__global__ void __launch_bounds__(256) k_ffn(
    const float* __restrict__ W1, const float* __restrict__ b1,
    const float* __restrict__ W2, const float* __restrict__ b2,
    const float* __restrict__ g2, const float* __restrict__ be2,
    float* __restrict__ out)
{
    extern __shared__ float sm[];
    float* W1s   = sm;                        // 16384
    float* W2t   = sm + 16384;                // 256*68
    float* b1s   = W2t + NFF*W2T_STRIDE;      // 256
    float* b2s   = b1s + 256;                 // 64
    float* g2s   = b2s + 64;                  // 64
    float* be2s  = g2s + 64;                  // 64
    float* stage = be2s + 64;                 // 64*128

    for (int i = threadIdx.x; i < NFF*NE; i += 256) {
        W1s[i] = W1[i];
        int d = i >> 8, j = i & 255;          // W2 is [E][FF]
        W2t[j*W2T_STRIDE + d] = W2[i];
    }
    for (int i = threadIdx.x; i < NFF; i += 256) b1s[i] = b1[i];
    if (threadIdx.x < 64) {
        b2s[threadIdx.x]  = b2[threadIdx.x];
        g2s[threadIdx.x]  = g2[threadIdx.x];
        be2s[threadIdx.x] = be2[threadIdx.x];
    }
    __syncthreads();

    int tl   = threadIdx.x & 127;
    int half = threadIdx.x >> 7;              // 0 or 1 (warp-uniform)
    int n = blockIdx.x * 128 + tl;

    u64 qv2[32];
    const float4* qp = (const float4*)(g_qo + (size_t)n * NE);
#pragma unroll
    for (int c = 0; c < 16; ++c) {
        float4 t = qp[c];
        qv2[2*c]   = pk(t.x, t.y);
        qv2[2*c+1] = pk(t.z, t.w);
    }

    u64 f2[32];
#pragma unroll
    for (int i = 0; i < 32; ++i) f2[i] = 0;

    unsigned w1b = smaddr(W1s);
    unsigned w2b = smaddr(W2t);

    int j0 = half * 128;
#pragma unroll 2
    for (int jj = 0; jj < 128; ++jj) {
        int j = j0 + jj;
        float s = dot64(w1b + j*256, qv2) + b1s[j];
        s = fmaxf(s, 0.0f);
        u64 ss = pk(s, s);
        unsigned wr = w2b + j*272;
#pragma unroll
        for (int t = 0; t < 16; ++t) {
            u64 w0, w1;
            lds16(wr + t*16, w0, w1);
            f2[2*t]   = f2fma(ss, w0, f2[2*t]);
            f2[2*t+1] = f2fma(ss, w1, f2[2*t+1]);
        }
    }

    // half 1 publishes its partials
    if (half == 1) {
#pragma unroll
        for (int i = 0; i < 32; ++i) {
            float a, b; upk(f2[i], a, b);
            stage[(2*i)*128 + tl]   = a;
            stage[(2*i+1)*128 + tl] = b;
        }
    }
    __syncthreads();

    if (half == 0) {
        float f[NE];
#pragma unroll
        for (int i = 0; i < 32; ++i) {
            float a, b; upk(f2[i], a, b);
            f[2*i]   = a + stage[(2*i)*128 + tl]   + b2s[2*i];
            f[2*i+1] = b + stage[(2*i+1)*128 + tl] + b2s[2*i+1];
        }
        const float4* x1p = (const float4*)(g_x1 + (size_t)n * NE);
#pragma unroll
        for (int c = 0; c < 16; ++c) {
            float4 t = x1p[c];
            f[4*c+0] += t.x; f[4*c+1] += t.y; f[4*c+2] += t.z; f[4*c+3] += t.w;
        }
        float sum = 0.f, sq = 0.f;
#pragma unroll
        for (int j = 0; j < NE; ++j) { sum += f[j]; sq += f[j]*f[j]; }
        float m = sum * (1.0f/NE);
        float var = sq * (1.0f/NE) - m*m;
        float inv = rsqrtf(var + 1e-5f);

        float4* op = (float4*)(out + (size_t)n * NE);
#pragma unroll
        for (int c = 0; c < 16; ++c) {
            float v0 = (f[4*c+0]-m)*inv*g2s[4*c+0] + be2s[4*c+0];
            float v1 = (f[4*c+1]-m)*inv*g2s[4*c+1] + be2s[4*c+1];
            float v2 = (f[4*c+2]-m)*inv*g2s[4*c+2] + be2s[4*c+2];
            float v3 = (f[4*c+3]-m)*inv*g2s[4*c+3] + be2s[4*c+3];
            op[c] = make_float4(v0, v1, v2, v3);
        }
    }
}

// ============================================================
// launch
// ============================================================
#define SMEM_QKV ((3*4096 + 3*64) * 4)
#define SMEM_ATT (2 * NT * NDK * 4)
#define SMEM_OPR ((4096 + 3*64 + 64*128) * 4)
#define SMEM_FFN ((NFF*NE + NFF*W2T_STRIDE + NFF + 3*64 + 64*128) * 4)

extern "C" void kernel_launch(void* const* d_in, const int* in_sizes, int n_in,
                              void* d_out, int out_size)
{
    const float* x   = (const float*)d_in[0];
    const float* Wq  = (const float*)d_in[1];
    const float* bq  = (const float*)d_in[2];
    const float* Wk  = (const float*)d_in[3];
    const float* bk  = (const float*)d_in[4];
    const float* Wv  = (const float*)d_in[5];
    const float* bv  = (const float*)d_in[6];
    const float* Wo  = (const float*)d_in[7];
    const float* bo  = (const float*)d_in[8];
    const float* thA = (const float*)d_in[9];
    const float* thF = (const float*)d_in[10];
    const float* W1  = (const float*)d_in[11];
    const float* b1  = (const float*)d_in[12];
    const float* W2  = (const float*)d_in[13];
    const float* b2  = (const float*)d_in[14];
    const float* g1  = (const float*)d_in[15];
    const float* be1 = (const float*)d_in[16];
    const float* g2  = (const float*)d_in[17];
    const float* be2 = (const float*)d_in[18];
    float* out = (float*)d_out;

    cudaFuncSetAttribute(k_qkv,   cudaFuncAttributeMaxDynamicSharedMemorySize, SMEM_QKV);
    cudaFuncSetAttribute(k_attn,  cudaFuncAttributeMaxDynamicSharedMemorySize, SMEM_ATT);
    cudaFuncSetAttribute(k_oproj, cudaFuncAttributeMaxDynamicSharedMemorySize, SMEM_OPR);
    cudaFuncSetAttribute(k_ffn,   cudaFuncAttributeMaxDynamicSharedMemorySize, SMEM_FFN);

    k_qkv<<<NTOK/128, 512, SMEM_QKV>>>(x, Wq, bq, Wk, bk, Wv, bv, thA);
    dim3 ga(NB*NH, NT/512);
    k_attn<<<ga, 512, SMEM_ATT>>>();
    k_oproj<<<NTOK/128, 512, SMEM_OPR>>>(x, Wo, bo, g1, be1, thF);
    k_ffn<<<NTOK/128, 256, SMEM_FFN>>>(W1, b1, W2, b2, g2, be2, out);
}

// round 6
// speedup vs baseline: 1.0049x; 1.0049x over previous
#include <cuda_runtime.h>
#include <math.h>

#define NB 8
#define NT 2048
#define NE 64
#define NH 8
#define NDK 8
#define NFF 256
#define NTOK (NB*NT)
#define W2T_STRIDE 68

typedef unsigned long long u64;

// ---- scratch (static device globals) ----
__device__ float g_Q[NTOK*NE];
__device__ float g_K[NTOK*NE];
__device__ float g_V[NTOK*NE];
__device__ float g_attn[NTOK*NE];
__device__ float g_x1[NTOK*NE];
__device__ float g_qo[NTOK*NE];

// ---- f32x2 packed helpers ----
__device__ __forceinline__ u64 pk(float a, float b) {
    u64 r; asm("mov.b64 %0,{%1,%2};" : "=l"(r) : "f"(a), "f"(b)); return r;
}
__device__ __forceinline__ void upk(u64 v, float& a, float& b) {
    asm("mov.b64 {%0,%1},%2;" : "=f"(a), "=f"(b) : "l"(v));
}
__device__ __forceinline__ u64 f2mul(u64 a, u64 b) {
    u64 r; asm("mul.rn.f32x2 %0,%1,%2;" : "=l"(r) : "l"(a), "l"(b)); return r;
}
__device__ __forceinline__ u64 f2fma(u64 a, u64 b, u64 c) {
    u64 r; asm("fma.rn.f32x2 %0,%1,%2,%3;" : "=l"(r) : "l"(a), "l"(b), "l"(c)); return r;
}
__device__ __forceinline__ u64 f2add(u64 a, u64 b) {
    u64 r; asm("add.rn.f32x2 %0,%1,%2;" : "=l"(r) : "l"(a), "l"(b)); return r;
}
__device__ __forceinline__ void lds16(unsigned addr, u64& a, u64& b) {
    asm volatile("ld.shared.v2.u64 {%0,%1},[%2];" : "=l"(a), "=l"(b) : "r"(addr));
}
__device__ __forceinline__ float ex2f(float x) {
    float r; asm("ex2.approx.f32 %0,%1;" : "=f"(r) : "f"(x)); return r;
}
__device__ __forceinline__ unsigned smaddr(const void* p) {
    unsigned r;
    asm("{ .reg .u64 t; cvta.to.shared.u64 t, %1; cvt.u32.u64 %0, t; }" : "=r"(r) : "l"(p));
    return r;
}

// 64-float dot: smem row (broadcast) vs packed register vector a2[32].
__device__ __forceinline__ float dot64(unsigned addr, const u64* a2) {
    u64 w0, w1, s0, s1;
    lds16(addr, w0, w1);
    s0 = f2mul(a2[0], w0);
    s1 = f2mul(a2[1], w1);
#pragma unroll
    for (int t = 1; t < 16; ++t) {
        lds16(addr + t*16, w0, w1);
        s0 = f2fma(a2[2*t],   w0, s0);
        s1 = f2fma(a2[2*t+1], w1, s1);
    }
    s0 = f2add(s0, s1);
    float lo, hi; upk(s0, lo, hi);
    return lo + hi;
}

// ============================================================
// K1: QKV proj + bias + cos(.+theta). 512 thr = 128 tokens x 4 j-slices.
// ============================================================
__global__ void __launch_bounds__(512) k_qkv(
    const float* __restrict__ x,
    const float* __restrict__ Wq, const float* __restrict__ bq,
    const float* __restrict__ Wk, const float* __restrict__ bk,
    const float* __restrict__ Wv, const float* __restrict__ bv,
    const float* __restrict__ thA)
{
    extern __shared__ float sm[];
    float* Wqs = sm;
    float* Wks = sm + 4096;
    float* Wvs = sm + 8192;
    float* bqs = sm + 12288;
    float* bks = sm + 12352;
    float* bvs = sm + 12416;

    for (int i = threadIdx.x; i < 4096; i += 512) {
        Wqs[i] = Wq[i]; Wks[i] = Wk[i]; Wvs[i] = Wv[i];
    }
    if (threadIdx.x < 64) {
        bqs[threadIdx.x] = bq[threadIdx.x];
        bks[threadIdx.x] = bk[threadIdx.x];
        bvs[threadIdx.x] = bv[threadIdx.x];
    }
    __syncthreads();

    int tok   = blockIdx.x * 128 + (threadIdx.x & 127);
    int slice = threadIdx.x >> 7;          // 0..3 (warp-uniform)

    u64 xr2[32];
    const float4* xp = (const float4*)(x + (size_t)tok * NE);
#pragma unroll
    for (int c = 0; c < 16; ++c) {
        float4 t = xp[c];
        xr2[2*c]   = pk(t.x, t.y);
        xr2[2*c+1] = pk(t.z, t.w);
    }
    float th = *thA;
    unsigned wqb = smaddr(Wqs), wkb = smaddr(Wks), wvb = smaddr(Wvs);

    float4* Qo = (float4*)(g_Q + (size_t)tok * NE);
    float4* Ko = (float4*)(g_K + (size_t)tok * NE);
    float4* Vo = (float4*)(g_V + (size_t)tok * NE);

#pragma unroll
    for (int c = 0; c < 4; ++c) {
        float oq[4], ok[4], ov[4];
#pragma unroll
        for (int u = 0; u < 4; ++u) {
            int j = slice*16 + 4*c + u;
            oq[u] = __cosf(dot64(wqb + j*256, xr2) + bqs[j] + th);
            ok[u] = __cosf(dot64(wkb + j*256, xr2) + bks[j] + th);
            ov[u] = __cosf(dot64(wvb + j*256, xr2) + bvs[j] + th);
        }
        Qo[slice*4 + c] = make_float4(oq[0], oq[1], oq[2], oq[3]);
        Ko[slice*4 + c] = make_float4(ok[0], ok[1], ok[2], ok[3]);
        Vo[slice*4 + c] = make_float4(ov[0], ov[1], ov[2], ov[3]);
    }
}

// ============================================================
// K2: attention. 512 threads (16 warps/SM), grid (64 bh, 4 q-tiles).
// K pair-interleaved in smem; softmax without max-subtraction.
// ============================================================
__global__ void __launch_bounds__(512) k_attn()
{
    extern __shared__ float sm[];
    char* smc = (char*)sm;
    int tid = threadIdx.x;
    int bh = blockIdx.x;
    int b = bh >> 3, h = bh & 7;

    const float4* Kg4 = (const float4*)g_K;
    const float4* Vg4 = (const float4*)g_V;
    size_t rowbase = (size_t)b * NT * 16 + h * 2;   // float4 units

    for (int i = tid; i < NT*2; i += 512) {
        int s = i >> 1, half = i & 1;
        float4 t = Kg4[rowbase + (size_t)s*16 + half];
        int p = s >> 1, lane = s & 1;
        char* dst = smc + p*64 + half*32 + lane*4;
        *(float*)(dst +  0) = t.x;
        *(float*)(dst +  8) = t.y;
        *(float*)(dst + 16) = t.z;
        *(float*)(dst + 24) = t.w;
        ((float4*)(smc + 65536))[i] = Vg4[rowbase + (size_t)s*16 + half];
    }
    __syncthreads();

    int q = blockIdx.y * 512 + tid;
    const float QS = 0.35355339059327373f * 1.4426950408889634f; // 1/sqrt(8)*log2e
    float4 qa = ((const float4*)g_Q)[rowbase + (size_t)q*16];
    float4 qb = ((const float4*)g_Q)[rowbase + (size_t)q*16 + 1];
    float t0 = qa.x*QS, t1 = qa.y*QS, t2 = qa.z*QS, t3 = qa.w*QS;
    float t4 = qb.x*QS, t5 = qb.y*QS, t6 = qb.z*QS, t7 = qb.w*QS;
    u64 qd0 = pk(t0,t0), qd1 = pk(t1,t1), qd2 = pk(t2,t2), qd3 = pk(t3,t3);
    u64 qd4 = pk(t4,t4), qd5 = pk(t5,t5), qd6 = pk(t6,t6), qd7 = pk(t7,t7);

    unsigned kb = smaddr(smc);
    unsigned vb = kb + 65536;
    u64 a0 = 0, a1 = 0, a2 = 0, a3 = 0, denP = 0;

#pragma unroll 4
    for (int p = 0; p < NT/2; ++p) {
        u64 p0,p1,p2,p3,p4,p5,p6,p7;
        unsigned ka = kb + p*64;
        lds16(ka,    p0, p1);
        lds16(ka+16, p2, p3);
        lds16(ka+32, p4, p5);
        lds16(ka+48, p6, p7);
        u64 d = f2mul(qd0, p0);
        d = f2fma(qd1, p1, d);
        d = f2fma(qd2, p2, d);
        d = f2fma(qd3, p3, d);
        d = f2fma(qd4, p4, d);
        d = f2fma(qd5, p5, d);
        d = f2fma(qd6, p6, d);
        d = f2fma(qd7, p7, d);
        float lo, hi; upk(d, lo, hi);
        float e0 = ex2f(lo), e1 = ex2f(hi);
        denP = f2add(denP, pk(e0, e1));
        u64 ee0 = pk(e0, e0), ee1 = pk(e1, e1);
        u64 v0,v1,v2,v3,v4,v5,v6,v7;
        unsigned va = vb + p*64;
        lds16(va,    v0, v1);
        lds16(va+16, v2, v3);
        lds16(va+32, v4, v5);
        lds16(va+48, v6, v7);
        a0 = f2fma(ee0, v0, a0);
        a1 = f2fma(ee0, v1, a1);
        a2 = f2fma(ee0, v2, a2);
        a3 = f2fma(ee0, v3, a3);
        a0 = f2fma(ee1, v4, a0);
        a1 = f2fma(ee1, v5, a1);
        a2 = f2fma(ee1, v6, a2);
        a3 = f2fma(ee1, v7, a3);
    }

    float dl, dh; upk(denP, dl, dh);
    float inv = 1.0f / (dl + dh);
    float o0,o1,o2,o3,o4,o5,o6,o7;
    upk(a0, o0, o1); upk(a1, o2, o3); upk(a2, o4, o5); upk(a3, o6, o7);
    float4* op = (float4*)(g_attn + ((size_t)(b*NT + q)) * NE + h * NDK);
    op[0] = make_float4(o0*inv, o1*inv, o2*inv, o3*inv);
    op[1] = make_float4(o4*inv, o5*inv, o6*inv, o7*inv);
}

// ============================================================
// K3: out-proj + residual + LN1 -> x1, qo. 512 thr = 128 tokens x 4 slices,
// staged through smem [j][token].
// ============================================================
__global__ void __launch_bounds__(512) k_oproj(
    const float* __restrict__ x,
    const float* __restrict__ Wo, const float* __restrict__ bo,
    const float* __restrict__ g1, const float* __restrict__ be1,
    const float* __restrict__ thF)
{
    extern __shared__ float sm[];
    float* Wos   = sm;             // 4096
    float* bos   = sm + 4096;      // 64
    float* g1s   = sm + 4160;      // 64
    float* be1s  = sm + 4224;      // 64
    float* stage = sm + 4288;      // 64*128

    for (int i = threadIdx.x; i < 4096; i += 512) Wos[i] = Wo[i];
    if (threadIdx.x < 64) {
        bos[threadIdx.x]  = bo[threadIdx.x];
        g1s[threadIdx.x]  = g1[threadIdx.x];
        be1s[threadIdx.x] = be1[threadIdx.x];
    }
    __syncthreads();

    int tl    = threadIdx.x & 127;             // local token
    int slice = threadIdx.x >> 7;              // 0..3
    int n = blockIdx.x * 128 + tl;

    u64 a2r[32];
    const float4* ap = (const float4*)(g_attn + (size_t)n * NE);
#pragma unroll
    for (int c = 0; c < 16; ++c) {
        float4 t = ap[c];
        a2r[2*c]   = pk(t.x, t.y);
        a2r[2*c+1] = pk(t.z, t.w);
    }
    unsigned wob = smaddr(Wos);

#pragma unroll
    for (int u = 0; u < 16; ++u) {
        int j = slice*16 + u;
        stage[j*128 + tl] = dot64(wob + j*256, a2r) + bos[j];
    }
    __syncthreads();

    if (threadIdx.x < 128) {
        const float4* xp = (const float4*)(x + (size_t)n * NE);
        float o[NE];
        float sum = 0.f, sq = 0.f;
#pragma unroll
        for (int c = 0; c < 16; ++c) {
            float xt[4];
            *(float4*)xt = xp[c];
#pragma unroll
            for (int u = 0; u < 4; ++u) {
                int j = 4*c + u;
                float t = stage[j*128 + tl] + xt[u];
                o[j] = t;
                sum += t;
                sq  += t * t;
            }
        }
        float m = sum * (1.0f/NE);
        float var = sq * (1.0f/NE) - m*m;
        float inv = rsqrtf(var + 1e-5f);
        float cth = __cosf(*thF);

        float4* x1p = (float4*)(g_x1 + (size_t)n * NE);
        float4* qop = (float4*)(g_qo + (size_t)n * NE);
#pragma unroll
        for (int c = 0; c < 16; ++c) {
            float v[4], w[4];
#pragma unroll
            for (int u = 0; u < 4; ++u) {
                int j = 4*c + u;
                v[u] = (o[j] - m) * inv * g1s[j] + be1s[j];
                w[u] = __cosf(v[u]) * cth;
            }
            x1p[c] = make_float4(v[0], v[1], v[2], v[3]);
            qop[c] = make_float4(w[0], w[1], w[2], w[3]);
        }
    }
}

// ============================================================
// K4: FFN + residual + LN2 -> out. 256 thr = 128 tokens x 2 halves of the
// 256 FF rows; partials combined via smem stage.
// ============================================================
__global__ void __launch_bounds__(256) k_ffn(
    const float* __restrict__ W1, const float* __restrict__ b1,
    const float* __restrict__ W2, const float* __restrict__ b2,
    const float* __restrict__ g2, const float* __restrict__ be2,
    float* __restrict__ out)
{
    extern __shared__ float sm[];
    float* W1s   = sm;                        // 16384
    float* W2t   = sm + 16384;                // 256*68
    float* b1s   = W2t + NFF*W2T_STRIDE;      // 256
    float* b2s   = b1s + 256;                 // 64
    float* g2s   = b2s + 64;                  // 64
    float* be2s  = g2s + 64;                  // 64
    float* stage = be2s + 64;                 // 64*128

    for (int i = threadIdx.x; i < NFF*NE; i += 256) {
        W1s[i] = W1[i];
        int d = i >> 8, j = i & 255;          // W2 is [E][FF]
        W2t[j*W2T_STRIDE + d] = W2[i];
    }
    for (int i = threadIdx.x; i < NFF; i += 256) b1s[i] = b1[i];
    if (threadIdx.x < 64) {
        b2s[threadIdx.x]  = b2[threadIdx.x];
        g2s[threadIdx.x]  = g2[threadIdx.x];
        be2s[threadIdx.x] = be2[threadIdx.x];
    }
    __syncthreads();

    int tl   = threadIdx.x & 127;
    int half = threadIdx.x >> 7;              // 0 or 1 (warp-uniform)
    int n = blockIdx.x * 128 + tl;

    u64 qv2[32];
    const float4* qp = (const float4*)(g_qo + (size_t)n * NE);
#pragma unroll
    for (int c = 0; c < 16; ++c) {
        float4 t = qp[c];
        qv2[2*c]   = pk(t.x, t.y);
        qv2[2*c+1] = pk(t.z, t.w);
    }

    u64 f2[32];
#pragma unroll
    for (int i = 0; i < 32; ++i) f2[i] = 0;

    unsigned w1b = smaddr(W1s);
    unsigned w2b = smaddr(W2t);

    int j0 = half * 128;
#pragma unroll 2
    for (int jj = 0; jj < 128; ++jj) {
        int j = j0 + jj;
        float s = dot64(w1b + j*256, qv2) + b1s[j];
        s = fmaxf(s, 0.0f);
        u64 ss = pk(s, s);
        unsigned wr = w2b + j*272;
#pragma unroll
        for (int t = 0; t < 16; ++t) {
            u64 w0, w1;
            lds16(wr + t*16, w0, w1);
            f2[2*t]   = f2fma(ss, w0, f2[2*t]);
            f2[2*t+1] = f2fma(ss, w1, f2[2*t+1]);
        }
    }

    // half 1 publishes its partials
    if (half == 1) {
#pragma unroll
        for (int i = 0; i < 32; ++i) {
            float a, b; upk(f2[i], a, b);
            stage[(2*i)*128 + tl]   = a;
            stage[(2*i+1)*128 + tl] = b;
        }
    }
    __syncthreads();

    if (half == 0) {
        float f[NE];
#pragma unroll
        for (int i = 0; i < 32; ++i) {
            float a, b; upk(f2[i], a, b);
            f[2*i]   = a + stage[(2*i)*128 + tl]   + b2s[2*i];
            f[2*i+1] = b + stage[(2*i+1)*128 + tl] + b2s[2*i+1];
        }
        const float4* x1p = (const float4*)(g_x1 + (size_t)n * NE);
#pragma unroll
        for (int c = 0; c < 16; ++c) {
            float4 t = x1p[c];
            f[4*c+0] += t.x; f[4*c+1] += t.y; f[4*c+2] += t.z; f[4*c+3] += t.w;
        }
        float sum = 0.f, sq = 0.f;
#pragma unroll
        for (int j = 0; j < NE; ++j) { sum += f[j]; sq += f[j]*f[j]; }
        float m = sum * (1.0f/NE);
        float var = sq * (1.0f/NE) - m*m;
        float inv = rsqrtf(var + 1e-5f);

        float4* op = (float4*)(out + (size_t)n * NE);
#pragma unroll
        for (int c = 0; c < 16; ++c) {
            float v0 = (f[4*c+0]-m)*inv*g2s[4*c+0] + be2s[4*c+0];
            float v1 = (f[4*c+1]-m)*inv*g2s[4*c+1] + be2s[4*c+1];
            float v2 = (f[4*c+2]-m)*inv*g2s[4*c+2] + be2s[4*c+2];
            float v3 = (f[4*c+3]-m)*inv*g2s[4*c+3] + be2s[4*c+3];
            op[c] = make_float4(v0, v1, v2, v3);
        }
    }
}

// ============================================================
// launch
// ============================================================
#define SMEM_QKV ((3*4096 + 3*64) * 4)
#define SMEM_ATT (2 * NT * NDK * 4)
#define SMEM_OPR ((4096 + 3*64 + 64*128) * 4)
#define SMEM_FFN ((NFF*NE + NFF*W2T_STRIDE + NFF + 3*64 + 64*128) * 4)

extern "C" void kernel_launch(void* const* d_in, const int* in_sizes, int n_in,
                              void* d_out, int out_size)
{
    const float* x   = (const float*)d_in[0];
    const float* Wq  = (const float*)d_in[1];
    const float* bq  = (const float*)d_in[2];
    const float* Wk  = (const float*)d_in[3];
    const float* bk  = (const float*)d_in[4];
    const float* Wv  = (const float*)d_in[5];
    const float* bv  = (const float*)d_in[6];
    const float* Wo  = (const float*)d_in[7];
    const float* bo  = (const float*)d_in[8];
    const float* thA = (const float*)d_in[9];
    const float* thF = (const float*)d_in[10];
    const float* W1  = (const float*)d_in[11];
    const float* b1  = (const float*)d_in[12];
    const float* W2  = (const float*)d_in[13];
    const float* b2  = (const float*)d_in[14];
    const float* g1  = (const float*)d_in[15];
    const float* be1 = (const float*)d_in[16];
    const float* g2  = (const float*)d_in[17];
    const float* be2 = (const float*)d_in[18];
    float* out = (float*)d_out;

    cudaFuncSetAttribute(k_qkv,   cudaFuncAttributeMaxDynamicSharedMemorySize, SMEM_QKV);
    cudaFuncSetAttribute(k_attn,  cudaFuncAttributeMaxDynamicSharedMemorySize, SMEM_ATT);
    cudaFuncSetAttribute(k_oproj, cudaFuncAttributeMaxDynamicSharedMemorySize, SMEM_OPR);
    cudaFuncSetAttribute(k_ffn,   cudaFuncAttributeMaxDynamicSharedMemorySize, SMEM_FFN);

    k_qkv<<<NTOK/128, 512, SMEM_QKV>>>(x, Wq, bq, Wk, bk, Wv, bv, thA);
    dim3 ga(NB*NH, NT/512);
    k_attn<<<ga, 512, SMEM_ATT>>>();
    k_oproj<<<NTOK/128, 512, SMEM_OPR>>>(x, Wo, bo, g1, be1, thF);
    k_ffn<<<NTOK/128, 256, SMEM_FFN>>>(W1, b1, W2, b2, g2, be2, out);
}